// round 6
// baseline (speedup 1.0000x reference)
#include <cuda_runtime.h>
#include <cuda_bf16.h>
#include <cstdint>
#include <cstddef>

#define LL   6
#define TT   256
#define NNH  128
#define DDIM 512
#define HH   8
#define DHH  64
#define DFF  2048
#define SSL  512

typedef unsigned long long u64x2;

__device__ __forceinline__ u64x2 pk2(float a, float b) {
    u64x2 r; asm("mov.b64 %0, {%1, %2};" : "=l"(r) : "f"(a), "f"(b)); return r;
}
__device__ __forceinline__ float2 upk(u64x2 v) {
    float2 r; asm("mov.b64 {%0, %1}, %2;" : "=f"(r.x), "=f"(r.y) : "l"(v)); return r;
}
__device__ __forceinline__ u64x2 ffma2(u64x2 a, u64x2 b, u64x2 c) {
    u64x2 d; asm("fma.rn.f32x2 %0, %1, %2, %3;" : "=l"(d) : "l"(a), "l"(b), "l"(c)); return d;
}
__device__ __forceinline__ u64x2 fmul2(u64x2 a, u64x2 b) {
    u64x2 d; asm("mul.rn.f32x2 %0, %1, %2;" : "=l"(d) : "l"(a), "l"(b)); return d;
}

// scratch (__device__ globals; no allocation allowed)
__device__ float  g_tgt [NNH * DDIM];
__device__ float  g_tmp [NNH * DDIM];
__device__ float  g_q   [NNH * DDIM];
__device__ float  g_o   [NNH * DDIM];
__device__ float  g_qt  [NNH * HH * DDIM];
__device__ float  g_ctx [NNH * HH * DDIM];
__device__ float  g_ff  [NNH * DFF];
__device__ float  g_part[2 * NNH * DFF];
__device__ float  g_facc[NNH * 8 * HH * DDIM];
__device__ float2 g_fst [NNH * 8 * HH];

// ---------------- embedding + positional encoding ----------------
__global__ __launch_bounds__(128) void embed_kernel(
    const int* __restrict__ toks, const float* __restrict__ embd,
    const int* __restrict__ offp, float* __restrict__ out)
{
    int n = blockIdx.x, tid = threadIdx.x;
    const float* erow = embd + (size_t)toks[n] * DDIM;
    float off = (float)offp[0];
    const float c = -9.210340371976184f / (float)DDIM;
    float4 v;
#pragma unroll
    for (int j = 0; j < 4; j++) {
        int d = tid * 4 + j;
        float ang = off * expf((float)(d & ~1) * c);
        ((float*)&v)[j] = erow[d] + ((d & 1) ? cosf(ang) : sinf(ang));
    }
    *(float4*)(out + (size_t)n * DDIM + tid * 4) = v;
}

// ---------------- layernorm over D=512, block per row ----------------
__global__ __launch_bounds__(128) void ln_kernel(
    const float* __restrict__ x, const float* __restrict__ w,
    const float* __restrict__ b, float* __restrict__ out)
{
    int n = blockIdx.x, t = threadIdx.x, warp = t >> 5, lane = t & 31;
    float4 xv = *(const float4*)(x + (size_t)n * DDIM + t * 4);
    float s  = xv.x + xv.y + xv.z + xv.w;
    float sq = xv.x*xv.x + xv.y*xv.y + xv.z*xv.z + xv.w*xv.w;
#pragma unroll
    for (int off = 16; off > 0; off >>= 1) {
        s  += __shfl_xor_sync(0xffffffffu, s,  off);
        sq += __shfl_xor_sync(0xffffffffu, sq, off);
    }
    __shared__ float2 rb[4];
    if (lane == 0) rb[warp] = make_float2(s, sq);
    __syncthreads();
    float S = 0.f, Q = 0.f;
#pragma unroll
    for (int i = 0; i < 4; i++) { S += rb[i].x; Q += rb[i].y; }
    float mean = S * (1.0f / DDIM);
    float var  = Q * (1.0f / DDIM) - mean * mean;
    float r = rsqrtf(var + 1e-5f);
    float4 wv = *(const float4*)(w + t * 4);
    float4 bv = *(const float4*)(b + t * 4);
    float4 o;
    o.x = (xv.x - mean) * r * wv.x + bv.x;
    o.y = (xv.y - mean) * r * wv.y + bv.y;
    o.z = (xv.z - mean) * r * wv.z + bv.z;
    o.w = (xv.w - mean) * r * wv.w + bv.w;
    *(float4*)(out + (size_t)n * DDIM + t * 4) = o;
}

// ---------------- tiled GEMM: C[n,m] = sum_k A[n,k]*W[m,k] (WT: W[k,m]) ----
// 64 rows per block (grid.x=2), BM cols, 256 threads, z = h*KS + ks.
#define KC 16
template<int BM, int RM, bool WT>
__global__ __launch_bounds__(256) void gemm_kernel(
    const float* __restrict__ A, int lda, int aOffZ,
    const float* __restrict__ W, int ldw, int wOffZ,
    float* __restrict__ C, int ldc, int cOffZ, long partStride,
    const float* __restrict__ bias, int K, int KS, float scale, int relu)
{
    constexpr int RN = 4;
    __shared__ __align__(16) float As[KC][68];
    __shared__ __align__(16) float Ws[KC][BM + 4];
    int z = blockIdx.z, h = z / KS, ks = z - h * KS;
    long koff = (long)ks * K;
    A += (size_t)h * aOffZ + koff;
    if (WT) W += (size_t)h * wOffZ + (size_t)koff * ldw;
    else    W += (size_t)h * wOffZ + koff;
    C += (size_t)h * cOffZ + (size_t)ks * partStride;
    int n0 = blockIdx.x * 64, m0 = blockIdx.y * BM;
    int t = threadIdx.x, tx = t & 15, ty = t >> 4;

    u64x2 acc[RN][RM / 2];
#pragma unroll
    for (int i = 0; i < RN; i++)
#pragma unroll
        for (int j = 0; j < RM / 2; j++) acc[i][j] = pk2(0.f, 0.f);

    for (int kc = 0; kc < K; kc += KC) {
        {
            int row = t >> 2, k4 = (t & 3) * 4;
            float4 v = *(const float4*)&A[(size_t)(n0 + row) * lda + kc + k4];
            As[k4+0][row] = v.x; As[k4+1][row] = v.y;
            As[k4+2][row] = v.z; As[k4+3][row] = v.w;
        }
        if (WT) {
            int k = t >> 4, m4 = (t & 15) * 4;
            float4 v = *(const float4*)&W[(size_t)(kc + k) * ldw + m0 + m4];
            *(float4*)&Ws[k][m4] = v;
        } else if (BM == 64) {
            int row = t >> 2, k4 = (t & 3) * 4;
            float4 v = *(const float4*)&W[(size_t)(m0 + row) * ldw + kc + k4];
            Ws[k4+0][row] = v.x; Ws[k4+1][row] = v.y;
            Ws[k4+2][row] = v.z; Ws[k4+3][row] = v.w;
        } else {
            int row = t >> 3, k2 = (t & 7) * 2;
            float2 v = *(const float2*)&W[(size_t)(m0 + row) * ldw + kc + k2];
            Ws[k2+0][row] = v.x; Ws[k2+1][row] = v.y;
        }
        __syncthreads();
#pragma unroll
        for (int kk = 0; kk < KC; kk++) {
            float4 av = *(const float4*)&As[kk][ty * 4];
            if (RM == 4) {
                u64x2 w0 = *(const u64x2*)&Ws[kk][tx * 4];
                u64x2 w1 = *(const u64x2*)&Ws[kk][tx * 4 + 2];
#pragma unroll
                for (int i = 0; i < RN; i++) {
                    float a = ((const float*)&av)[i];
                    u64x2 a2 = pk2(a, a);
                    acc[i][0] = ffma2(a2, w0, acc[i][0]);
                    acc[i][1] = ffma2(a2, w1, acc[i][1]);
                }
            } else {
                u64x2 w0 = *(const u64x2*)&Ws[kk][tx * 2];
#pragma unroll
                for (int i = 0; i < RN; i++) {
                    float a = ((const float*)&av)[i];
                    acc[i][0] = ffma2(pk2(a, a), w0, acc[i][0]);
                }
            }
        }
        __syncthreads();
    }
    int mc = m0 + tx * RM;
#pragma unroll
    for (int i = 0; i < RN; i++) {
        int row = n0 + ty * RN + i;
        float out[RM];
#pragma unroll
        for (int j = 0; j < RM / 2; j++) {
            float2 f = upk(acc[i][j]); out[j*2] = f.x; out[j*2+1] = f.y;
        }
#pragma unroll
        for (int j = 0; j < RM; j++) {
            if (bias) out[j] += bias[mc + j];
            out[j] *= scale;
            if (relu) out[j] = fmaxf(out[j], 0.f);
        }
        float* cp = C + (size_t)row * ldc + mc;
        if (RM == 4) { float4 v = {out[0], out[1], out[2], out[3]}; *(float4*)cp = v; }
        else         { float2 v = {out[0], out[1]};                 *(float2*)cp = v; }
    }
}

// split-K reduce: C = relu(scale*(sum_ks part + bias)) + res
__global__ __launch_bounds__(128) void reduce_kernel(
    const float* __restrict__ part, long PS, int KS,
    const float* __restrict__ bias, const float* __restrict__ res,
    float* __restrict__ C, int M, float scale, int relu)
{
    size_t idx = ((size_t)blockIdx.x * 128 + threadIdx.x) * 4;
    int mcol = (int)(idx % M);
    float4 v = make_float4(0.f, 0.f, 0.f, 0.f);
    for (int ks = 0; ks < KS; ks++) {
        float4 p = *(const float4*)(part + (size_t)ks * PS + idx);
        v.x += p.x; v.y += p.y; v.z += p.z; v.w += p.w;
    }
    if (bias) {
        float4 bb = *(const float4*)(bias + mcol);
        v.x += bb.x; v.y += bb.y; v.z += bb.z; v.w += bb.w;
    }
    v.x *= scale; v.y *= scale; v.z *= scale; v.w *= scale;
    if (relu) {
        v.x = fmaxf(v.x, 0.f); v.y = fmaxf(v.y, 0.f);
        v.z = fmaxf(v.z, 0.f); v.w = fmaxf(v.w, 0.f);
    }
    if (res) {
        float4 r = *(const float4*)(res + idx);
        v.x += r.x; v.y += r.y; v.z += r.z; v.w += r.w;
    }
    *(float4*)(C + idx) = v;
}

// ---------------- flash attention (folded projections) ----------------
__device__ __forceinline__ void f_load(u64x2* dst, const float* kvn,
    const float4* erow, int t, int Tmain, long rs, int lane)
{
    const float4* rp = (t < Tmain) ? (const float4*)(kvn + (size_t)t * rs) : erow;
#pragma unroll
    for (int qi = 0; qi < 4; qi++) {
        float4 v = __ldg(&rp[lane + 32 * qi]);
        dst[2*qi] = pk2(v.x, v.y); dst[2*qi+1] = pk2(v.z, v.w);
    }
}
__device__ __forceinline__ void f_step(const u64x2* kvp, const u64x2 qtr[2][8],
    const float qb[2], float nm, float mh[2], float sh[2], u64x2 acc[2][8])
{
    float sc[2];
#pragma unroll
    for (int hh = 0; hh < 2; hh++) {
        u64x2 d0 = pk2(0.f, 0.f), d1 = pk2(0.f, 0.f);
#pragma unroll
        for (int qi = 0; qi < 4; qi++) {
            d0 = ffma2(qtr[hh][2*qi],   kvp[2*qi],   d0);
            d1 = ffma2(qtr[hh][2*qi+1], kvp[2*qi+1], d1);
        }
        float2 f0 = upk(d0), f1 = upk(d1);
        sc[hh] = f0.x + f0.y + f1.x + f1.y;
    }
#pragma unroll
    for (int off = 16; off > 0; off >>= 1) {
        sc[0] += __shfl_xor_sync(0xffffffffu, sc[0], off);
        sc[1] += __shfl_xor_sync(0xffffffffu, sc[1], off);
    }
#pragma unroll
    for (int hh = 0; hh < 2; hh++) {
        float s = sc[hh] + qb[hh] + nm;
        float mn = fmaxf(mh[hh], s);
        float c0 = __expf(mh[hh] - mn), p = __expf(s - mn);
        sh[hh] = sh[hh] * c0 + p; mh[hh] = mn;
        u64x2 c2 = pk2(c0, c0), p2 = pk2(p, p);
#pragma unroll
        for (int qi = 0; qi < 8; qi++)
            acc[hh][qi] = ffma2(acc[hh][qi], c2, fmul2(kvp[qi], p2));
    }
}

__global__ __launch_bounds__(256) void flash_kernel(
    const float* __restrict__ qt, const float* __restrict__ qs,
    const float* __restrict__ bk, const float* __restrict__ kv,
    const float* __restrict__ extra, const unsigned char* __restrict__ mask,
    float2* __restrict__ fst, float* __restrict__ facc,
    int Tlen, int Tmain, long rs)
{
    int n = blockIdx.x;
    int w = threadIdx.x >> 5, lane = threadIdx.x & 31;
    int hp = w & 3, c = w >> 2, h0 = hp * 2;
    int seg = blockIdx.y * 2 + c;
    int ts = (seg * Tlen) >> 3, te = ((seg + 1) * Tlen) >> 3;

    u64x2 qtr[2][8];
#pragma unroll
    for (int hh = 0; hh < 2; hh++) {
        const float4* qp = (const float4*)(qt + ((size_t)n * HH + h0 + hh) * DDIM);
#pragma unroll
        for (int qi = 0; qi < 4; qi++) {
            float4 v = qp[lane + 32 * qi];
            qtr[hh][2*qi] = pk2(v.x, v.y); qtr[hh][2*qi+1] = pk2(v.z, v.w);
        }
    }
    float qb[2];
#pragma unroll
    for (int hh = 0; hh < 2; hh++) {
        int h = h0 + hh;
        float p = qs[(size_t)n * DDIM + h*64 + lane]      * bk[h*64 + lane]
                + qs[(size_t)n * DDIM + h*64 + 32 + lane] * bk[h*64 + 32 + lane];
#pragma unroll
        for (int off = 16; off > 0; off >>= 1)
            p += __shfl_xor_sync(0xffffffffu, p, off);
        qb[hh] = p;
    }
    float mh[2] = {-1e30f, -1e30f}, sh[2] = {0.f, 0.f};
    u64x2 acc[2][8];
#pragma unroll
    for (int hh = 0; hh < 2; hh++)
#pragma unroll
        for (int qi = 0; qi < 8; qi++) acc[hh][qi] = pk2(0.f, 0.f);

    const float* kvn = kv + (size_t)n * DDIM;
    const float4* erow = (const float4*)(extra + (size_t)n * DDIM);
    const unsigned char* mk = mask ? mask + (size_t)n * Tlen : nullptr;

    u64x2 A[8], B[8];
    if (ts < te) f_load(A, kvn, erow, ts, Tmain, rs, lane);
    int t = ts;
    while (t < te) {
        if (t + 1 < te) f_load(B, kvn, erow, t + 1, Tmain, rs, lane);
        f_step(A, qtr, qb, (mk && mk[t]) ? -1e9f : 0.f, mh, sh, acc);
        t++;
        if (t >= te) break;
        if (t + 1 < te) f_load(A, kvn, erow, t + 1, Tmain, rs, lane);
        f_step(B, qtr, qb, (mk && mk[t]) ? -1e9f : 0.f, mh, sh, acc);
        t++;
    }
#pragma unroll
    for (int hh = 0; hh < 2; hh++) {
        size_t base = ((size_t)n * 8 + seg) * HH + h0 + hh;
        if (lane == 0) fst[base] = make_float2(mh[hh], sh[hh]);
        float4* op = (float4*)(facc + base * DDIM);
#pragma unroll
        for (int qi = 0; qi < 4; qi++) {
            float2 a = upk(acc[hh][2*qi]), b = upk(acc[hh][2*qi+1]);
            float4 v = {a.x, a.y, b.x, b.y};
            op[lane + 32 * qi] = v;
        }
    }
}

__global__ __launch_bounds__(256) void merge_kernel(
    const float* __restrict__ facc, const float2* __restrict__ fst,
    float* __restrict__ ctx)
{
    int n = blockIdx.x, w = threadIdx.x >> 5, lane = threadIdx.x & 31;
    float2 st[8]; float M = -1e30f;
#pragma unroll
    for (int s = 0; s < 8; s++) {
        st[s] = fst[((size_t)n * 8 + s) * HH + w];
        M = fmaxf(M, st[s].x);
    }
    float S = 0.f;
#pragma unroll
    for (int s = 0; s < 8; s++) S += st[s].y * __expf(st[s].x - M);
    float inv = 1.f / S;
    float co[8];
#pragma unroll
    for (int s = 0; s < 8; s++) co[s] = __expf(st[s].x - M) * inv;
    float4 out[4];
#pragma unroll
    for (int qi = 0; qi < 4; qi++) out[qi] = make_float4(0.f, 0.f, 0.f, 0.f);
#pragma unroll
    for (int s = 0; s < 8; s++) {
        const float4* ap = (const float4*)(facc + (((size_t)n * 8 + s) * HH + w) * DDIM);
#pragma unroll
        for (int qi = 0; qi < 4; qi++) {
            float4 v = ap[lane + 32 * qi];
            out[qi].x += co[s]*v.x; out[qi].y += co[s]*v.y;
            out[qi].z += co[s]*v.z; out[qi].w += co[s]*v.w;
        }
    }
    float4* op = (float4*)(ctx + ((size_t)n * HH + w) * DDIM);
#pragma unroll
    for (int qi = 0; qi < 4; qi++) op[lane + 32 * qi] = out[qi];
}

// ---------------- host ----------------
static void gemm64(const float* A, int lda, int aOffZ,
                   const float* W, int ldw, int wOffZ, bool wt,
                   float* C, int ldc, int cOffZ, long PS, const float* bias,
                   int Kloc, int KS, int Hz, int Mz, float scale, int relu)
{
    dim3 g(2, Mz / 64, Hz * KS);
    if (wt)
        gemm_kernel<64,4,true><<<g,256>>>(A,lda,aOffZ,W,ldw,wOffZ,C,ldc,cOffZ,PS,bias,Kloc,KS,scale,relu);
    else
        gemm_kernel<64,4,false><<<g,256>>>(A,lda,aOffZ,W,ldw,wOffZ,C,ldc,cOffZ,PS,bias,Kloc,KS,scale,relu);
}
static void red(const float* part, long PS, int KS, const float* bias,
                const float* res, float* C, int M, float scale, int relu)
{
    reduce_kernel<<<(NNH * M) / 512, 128>>>(part, PS, KS, bias, res, C, M, scale, relu);
}

extern "C" void kernel_launch(void* const* d_in, const int* in_sizes, int n_in,
                              void* d_out, int out_size)
{
    (void)in_sizes; (void)n_in; (void)out_size;
    const int*   toks   = (const int*)  d_in[0];
    const float* cached = (const float*)d_in[1];
    const float* memory = (const float*)d_in[2];
    const unsigned char* mmask = (const unsigned char*)d_in[3];
    const float* embd   = (const float*)d_in[4];
    const float* Wqkv_s = (const float*)d_in[5];
    const float* bqkv_s = (const float*)d_in[6];
    const float* Wo_s   = (const float*)d_in[7];
    const float* bo_s   = (const float*)d_in[8];
    const float* Wqkv_c = (const float*)d_in[9];
    const float* bqkv_c = (const float*)d_in[10];
    const float* Wo_c   = (const float*)d_in[11];
    const float* bo_c   = (const float*)d_in[12];
    const float* W1     = (const float*)d_in[13];
    const float* b1     = (const float*)d_in[14];
    const float* W2     = (const float*)d_in[15];
    const float* b2     = (const float*)d_in[16];
    const float* ln1w   = (const float*)d_in[17];
    const float* ln1b   = (const float*)d_in[18];
    const float* ln2w   = (const float*)d_in[19];
    const float* ln2b   = (const float*)d_in[20];
    const float* ln3w   = (const float*)d_in[21];
    const float* ln3b   = (const float*)d_in[22];
    const int*   offp   = (const int*)  d_in[23];
    float* dout = (float*)d_out;

    float *tgt,*tmp,*q,*o,*qt,*ctx,*ff,*part,*facc; float2* fst;
    cudaGetSymbolAddress((void**)&tgt,  g_tgt);
    cudaGetSymbolAddress((void**)&tmp,  g_tmp);
    cudaGetSymbolAddress((void**)&q,    g_q);
    cudaGetSymbolAddress((void**)&o,    g_o);
    cudaGetSymbolAddress((void**)&qt,   g_qt);
    cudaGetSymbolAddress((void**)&ctx,  g_ctx);
    cudaGetSymbolAddress((void**)&ff,   g_ff);
    cudaGetSymbolAddress((void**)&part, g_part);
    cudaGetSymbolAddress((void**)&facc, g_facc);
    cudaGetSymbolAddress((void**)&fst,  g_fst);

    const long PS_D = (long)NNH * DDIM;
    embed_kernel<<<NNH, 128>>>(toks, embd, offp, tgt);

    for (int l = 0; l < LL; l++) {
        for (int pass = 0; pass < 2; pass++) {
            const float* Wqkv = (pass==0 ? Wqkv_s : Wqkv_c) + (size_t)l*3*DDIM*DDIM;
            const float* bqkv = (pass==0 ? bqkv_s : bqkv_c) + (size_t)l*3*DDIM;
            const float* Wo   = (pass==0 ? Wo_s   : Wo_c)   + (size_t)l*DDIM*DDIM;
            const float* bo   = (pass==0 ? bo_s   : bo_c)   + (size_t)l*DDIM;
            const float* lw   = (pass==0 ? ln1w : ln2w) + (size_t)l*DDIM;
            const float* lb   = (pass==0 ? ln1b : ln2b) + (size_t)l*DDIM;
            const float* kv   = (pass==0) ? cached + (size_t)l*TT*NNH*DDIM : memory;
            int Tlen  = (pass==0) ? TT + 1 : SSL;
            int Tmain = (pass==0) ? TT : SSL;
            const unsigned char* mk = (pass==0) ? nullptr : mmask;

            // q = 0.125*(tgt @ Wq^T + bq), split-K 4
            gemm64(tgt, DDIM,0, Wqkv, DDIM,0,false, part, DDIM,0, PS_D, nullptr,
                   DDIM/4,4, 1, DDIM, 1.f,0);
            red(part, PS_D, 4, bqkv, nullptr, q, DDIM, 0.125f, 0);
            // qt[n,h,:] = q[n,h*64:h*64+64] @ Wk_h  (WT path, z=head)
            gemm64(q, DDIM, DHH, Wqkv + DDIM*DDIM, DDIM, DHH*DDIM, true,
                   qt, HH*DDIM, DDIM, 0, nullptr, DHH,1, HH, DDIM, 1.f,0);
            // flash + merge -> ctx
            flash_kernel<<<dim3(NNH,4),256>>>(qt, q, bqkv + DDIM, kv, tgt, mk,
                                              fst, facc, Tlen, Tmain, PS_D);
            merge_kernel<<<NNH,256>>>(facc, fst, ctx);
            // o[n, h*64+j] = Wv_h @ ctx[n,h,:] + bv, split-K 2 per head
            {
                dim3 g(2, 2, HH * 2);
                gemm_kernel<32,2,false><<<g,256>>>(ctx, HH*DDIM, DDIM,
                    Wqkv + 2*DDIM*DDIM, DDIM, DHH*DDIM,
                    part, DDIM, DHH, PS_D, nullptr, DDIM/2, 2, 1.f, 0);
            }
            red(part, PS_D, 2, bqkv + 2*DDIM, nullptr, o, DDIM, 1.f, 0);
            // attn = o @ Wo^T + bo + tgt, split-K 4
            gemm64(o, DDIM,0, Wo, DDIM,0,false, part, DDIM,0, PS_D, nullptr,
                   DDIM/4,4, 1, DDIM, 1.f,0);
            red(part, PS_D, 4, bo, tgt, tmp, DDIM, 1.f, 0);
            ln_kernel<<<NNH,128>>>(tmp, lw, lb, tgt);
        }
        // FFN
        const float* W1l = W1 + (size_t)l*DFF*DDIM;
        const float* W2l = W2 + (size_t)l*DDIM*DFF;
        gemm64(tgt, DDIM,0, W1l, DDIM,0,false, part, DFF,0, (long)NNH*DFF, nullptr,
               DDIM/2,2, 1, DFF, 1.f,0);
        red(part, (long)NNH*DFF, 2, b1 + (size_t)l*DFF, nullptr, ff, DFF, 1.f, 1);
        gemm64(ff, DFF,0, W2l, DFF,0,false, part, DDIM,0, PS_D, nullptr,
               DFF/4,4, 1, DDIM, 1.f,0);
        red(part, PS_D, 4, b2 + (size_t)l*DDIM, tgt, tmp, DDIM, 1.f, 0);
        ln_kernel<<<NNH,128>>>(tmp, ln3w + (size_t)l*DDIM, ln3b + (size_t)l*DDIM,
                               (l == LL-1) ? dout : tgt);
    }
}

// round 7
// speedup vs baseline: 1.0932x; 1.0932x over previous
#include <cuda_runtime.h>
#include <cuda_bf16.h>
#include <cstdint>
#include <cstddef>

#define LL   6
#define TT   256
#define NNH  128
#define DDIM 512
#define HH   8
#define DHH  64
#define DFF  2048
#define SSL  512

typedef unsigned long long u64x2;

__device__ __forceinline__ u64x2 pk2(float a, float b) {
    u64x2 r; asm("mov.b64 %0, {%1, %2};" : "=l"(r) : "f"(a), "f"(b)); return r;
}
__device__ __forceinline__ float2 upk(u64x2 v) {
    float2 r; asm("mov.b64 {%0, %1}, %2;" : "=f"(r.x), "=f"(r.y) : "l"(v)); return r;
}
__device__ __forceinline__ u64x2 ffma2(u64x2 a, u64x2 b, u64x2 c) {
    u64x2 d; asm("fma.rn.f32x2 %0, %1, %2, %3;" : "=l"(d) : "l"(a), "l"(b), "l"(c)); return d;
}

// scratch (__device__ globals; no allocation allowed)
__device__ float  g_tgt [NNH * DDIM];
__device__ float  g_q   [NNH * DDIM];
__device__ float  g_o   [NNH * DDIM];
__device__ float  g_qt  [NNH * HH * DDIM];
__device__ float  g_ctx [NNH * HH * DDIM];
__device__ float  g_ff  [NNH * DFF];
__device__ float  g_part[8 * NNH * DDIM];   // 524288 floats; also covers 2*N*DFF
__device__ float  g_facc[NNH * 8 * HH * DDIM];
__device__ float2 g_fst [NNH * 8 * HH];

// ---------------- embedding + positional encoding ----------------
__global__ __launch_bounds__(128) void embed_kernel(
    const int* __restrict__ toks, const float* __restrict__ embd,
    const int* __restrict__ offp, float* __restrict__ out)
{
    int n = blockIdx.x, tid = threadIdx.x;
    const float* erow = embd + (size_t)toks[n] * DDIM;
    float off = (float)offp[0];
    const float c = -9.210340371976184f / (float)DDIM;
    float4 v;
#pragma unroll
    for (int j = 0; j < 4; j++) {
        int d = tid * 4 + j;
        float ang = off * expf((float)(d & ~1) * c);
        ((float*)&v)[j] = erow[d] + ((d & 1) ? cosf(ang) : sinf(ang));
    }
    *(float4*)(out + (size_t)n * DDIM + tid * 4) = v;
}

// ---------------- GEMM: C[n,m] = sum_k A[n,k]*W[m,k] (WT: W[k,m]) ----------
// 32x64 tile, 256 threads, double-buffered smem, z = h*KS + ks (split-K).
#define KC 16
template<bool WT>
__global__ __launch_bounds__(256) void gemm_kernel(
    const float* __restrict__ A, int lda, int aOffZ,
    const float* __restrict__ W, int ldw, int wOffZ,
    float* __restrict__ C, int ldc, int cOffZ, long partStride,
    const float* __restrict__ bias, int K, int KS, float scale, int relu)
{
    __shared__ __align__(16) float As[2][KC][34];
    __shared__ __align__(16) float Ws[2][KC][68];
    int z = blockIdx.z, h = z / KS, ks = z - h * KS;
    long koff = (long)ks * K;
    A += (size_t)h * aOffZ + koff;
    W += (size_t)h * wOffZ + (WT ? (size_t)koff * ldw : (size_t)koff);
    C += (size_t)h * cOffZ + (size_t)ks * partStride;
    int n0 = blockIdx.x * 32, m0 = blockIdx.y * 64;
    int t = threadIdx.x, tx = t & 15, ty = t >> 4;

    int ar  = t >> 3, ak  = (t & 7) * 2;   // A load lane
    int wr  = t >> 2, wk  = (t & 3) * 4;   // W load (row-major)
    int wtk = t >> 4, wtm = (t & 15) * 4;  // W load (transposed)

    u64x2 acc[2][2];
    acc[0][0] = acc[0][1] = acc[1][0] = acc[1][1] = pk2(0.f, 0.f);

    float2 ra = *(const float2*)&A[(size_t)(n0 + ar) * lda + ak];
    float4 rw;
    if (WT) rw = *(const float4*)&W[(size_t)wtk * ldw + m0 + wtm];
    else    rw = *(const float4*)&W[(size_t)(m0 + wr) * ldw + wk];

    int buf = 0;
    for (int kc = 0; kc < K; kc += KC) {
        As[buf][ak + 0][ar] = ra.x;
        As[buf][ak + 1][ar] = ra.y;
        if (WT) {
            *(float4*)&Ws[buf][wtk][wtm] = rw;
        } else {
            Ws[buf][wk + 0][wr] = rw.x; Ws[buf][wk + 1][wr] = rw.y;
            Ws[buf][wk + 2][wr] = rw.z; Ws[buf][wk + 3][wr] = rw.w;
        }
        __syncthreads();
        int kn = kc + KC;
        if (kn < K) {
            ra = *(const float2*)&A[(size_t)(n0 + ar) * lda + kn + ak];
            if (WT) rw = *(const float4*)&W[(size_t)(kn + wtk) * ldw + m0 + wtm];
            else    rw = *(const float4*)&W[(size_t)(m0 + wr) * ldw + kn + wk];
        }
#pragma unroll
        for (int kk = 0; kk < KC; kk++) {
            float2 av = *(const float2*)&As[buf][kk][ty * 2];
            u64x2 w0 = *(const u64x2*)&Ws[buf][kk][tx * 4];
            u64x2 w1 = *(const u64x2*)&Ws[buf][kk][tx * 4 + 2];
            u64x2 a0 = pk2(av.x, av.x), a1 = pk2(av.y, av.y);
            acc[0][0] = ffma2(a0, w0, acc[0][0]);
            acc[0][1] = ffma2(a0, w1, acc[0][1]);
            acc[1][0] = ffma2(a1, w0, acc[1][0]);
            acc[1][1] = ffma2(a1, w1, acc[1][1]);
        }
        buf ^= 1;
    }

    int mc = m0 + tx * 4;
#pragma unroll
    for (int i = 0; i < 2; i++) {
        int row = n0 + ty * 2 + i;
        float2 f0 = upk(acc[i][0]), f1 = upk(acc[i][1]);
        float out[4] = {f0.x, f0.y, f1.x, f1.y};
#pragma unroll
        for (int j = 0; j < 4; j++) {
            if (bias) out[j] += bias[mc + j];
            out[j] *= scale;
            if (relu) out[j] = fmaxf(out[j], 0.f);
        }
        float4 v = {out[0], out[1], out[2], out[3]};
        *(float4*)&C[(size_t)row * ldc + mc] = v;
    }
}

// split-K reduce: C = relu(scale*(sum_ks part + bias)) + res
__global__ __launch_bounds__(128) void reduce_kernel(
    const float* __restrict__ part, long PS, int KS,
    const float* __restrict__ bias, const float* __restrict__ res,
    float* __restrict__ C, int M, float scale, int relu)
{
    size_t idx = ((size_t)blockIdx.x * 128 + threadIdx.x) * 4;
    int mcol = (int)(idx % M);
    float4 v = make_float4(0.f, 0.f, 0.f, 0.f);
    for (int ks = 0; ks < KS; ks++) {
        float4 p = *(const float4*)(part + (size_t)ks * PS + idx);
        v.x += p.x; v.y += p.y; v.z += p.z; v.w += p.w;
    }
    if (bias) {
        float4 bb = *(const float4*)(bias + mcol);
        v.x += bb.x; v.y += bb.y; v.z += bb.z; v.w += bb.w;
    }
    v.x *= scale; v.y *= scale; v.z *= scale; v.w *= scale;
    if (relu) {
        v.x = fmaxf(v.x, 0.f); v.y = fmaxf(v.y, 0.f);
        v.z = fmaxf(v.z, 0.f); v.w = fmaxf(v.w, 0.f);
    }
    if (res) {
        float4 r = *(const float4*)(res + idx);
        v.x += r.x; v.y += r.y; v.z += r.z; v.w += r.w;
    }
    *(float4*)(C + idx) = v;
}

// fused split-K reduce + bias + residual + layernorm (block per row)
__global__ __launch_bounds__(128) void ln_red_kernel(
    const float* __restrict__ part, long PS, int KS,
    const float* __restrict__ bias, const float* __restrict__ res,
    const float* __restrict__ w, const float* __restrict__ b,
    float* __restrict__ out)
{
    int n = blockIdx.x, t = threadIdx.x, warp = t >> 5, lane = t & 31;
    size_t idx = (size_t)n * DDIM + t * 4;
    float4 xv = make_float4(0.f, 0.f, 0.f, 0.f);
    for (int ks = 0; ks < KS; ks++) {
        float4 p = *(const float4*)(part + (size_t)ks * PS + idx);
        xv.x += p.x; xv.y += p.y; xv.z += p.z; xv.w += p.w;
    }
    float4 bb = *(const float4*)(bias + t * 4);
    float4 rr = *(const float4*)(res + idx);
    xv.x += bb.x + rr.x; xv.y += bb.y + rr.y;
    xv.z += bb.z + rr.z; xv.w += bb.w + rr.w;

    float s  = xv.x + xv.y + xv.z + xv.w;
    float sq = xv.x*xv.x + xv.y*xv.y + xv.z*xv.z + xv.w*xv.w;
#pragma unroll
    for (int off = 16; off > 0; off >>= 1) {
        s  += __shfl_xor_sync(0xffffffffu, s,  off);
        sq += __shfl_xor_sync(0xffffffffu, sq, off);
    }
    __shared__ float2 rb[4];
    if (lane == 0) rb[warp] = make_float2(s, sq);
    __syncthreads();
    float S = 0.f, Q = 0.f;
#pragma unroll
    for (int i = 0; i < 4; i++) { S += rb[i].x; Q += rb[i].y; }
    float mean = S * (1.0f / DDIM);
    float var  = Q * (1.0f / DDIM) - mean * mean;
    float r = rsqrtf(var + 1e-5f);
    float4 wv = *(const float4*)(w + t * 4);
    float4 bv = *(const float4*)(b + t * 4);
    float4 o;
    o.x = (xv.x - mean) * r * wv.x + bv.x;
    o.y = (xv.y - mean) * r * wv.y + bv.y;
    o.z = (xv.z - mean) * r * wv.z + bv.z;
    o.w = (xv.w - mean) * r * wv.w + bv.w;
    *(float4*)(out + idx) = o;
}

// ---------------- flash attention (folded projections) ----------------
__device__ __forceinline__ void f_load(u64x2* dst, const float* kvn,
    const float4* erow, int t, int Tmain, long rs, int lane)
{
    const float4* rp = (t < Tmain) ? (const float4*)(kvn + (size_t)t * rs) : erow;
#pragma unroll
    for (int qi = 0; qi < 4; qi++) {
        float4 v = __ldg(&rp[lane + 32 * qi]);
        dst[2*qi] = pk2(v.x, v.y); dst[2*qi+1] = pk2(v.z, v.w);
    }
}
__device__ __forceinline__ void f_step(const u64x2* kvp, const u64x2 qtr[2][8],
    const float qb[2], float nm, float mh[2], float sh[2], u64x2 acc[2][8])
{
    float sc[2];
#pragma unroll
    for (int hh = 0; hh < 2; hh++) {
        u64x2 d0 = pk2(0.f, 0.f), d1 = pk2(0.f, 0.f);
#pragma unroll
        for (int qi = 0; qi < 4; qi++) {
            d0 = ffma2(qtr[hh][2*qi],   kvp[2*qi],   d0);
            d1 = ffma2(qtr[hh][2*qi+1], kvp[2*qi+1], d1);
        }
        float2 f0 = upk(d0), f1 = upk(d1);
        sc[hh] = f0.x + f0.y + f1.x + f1.y;
    }
#pragma unroll
    for (int off = 16; off > 0; off >>= 1) {
        sc[0] += __shfl_xor_sync(0xffffffffu, sc[0], off);
        sc[1] += __shfl_xor_sync(0xffffffffu, sc[1], off);
    }
#pragma unroll
    for (int hh = 0; hh < 2; hh++) {
        float s = sc[hh] + qb[hh] + nm;
        if (s <= mh[hh]) {          // common: max unchanged, p = exp(s-m)
            float p = __expf(s - mh[hh]);
            sh[hh] += p;
            u64x2 p2 = pk2(p, p);
#pragma unroll
            for (int qi = 0; qi < 8; qi++)
                acc[hh][qi] = ffma2(kvp[qi], p2, acc[hh][qi]);
        } else {                    // new max: p = 1, rescale olds
            float c0 = __expf(mh[hh] - s);
            sh[hh] = sh[hh] * c0 + 1.f;
            mh[hh] = s;
            u64x2 c2 = pk2(c0, c0);
#pragma unroll
            for (int qi = 0; qi < 8; qi++)
                acc[hh][qi] = ffma2(acc[hh][qi], c2, kvp[qi]);
        }
    }
}

__global__ __launch_bounds__(256) void flash_kernel(
    const float* __restrict__ qt, const float* __restrict__ qs,
    const float* __restrict__ bk, const float* __restrict__ kv,
    const float* __restrict__ extra, const unsigned char* __restrict__ mask,
    float2* __restrict__ fst, float* __restrict__ facc,
    int Tlen, int Tmain, long rs)
{
    int n = blockIdx.x;
    int w = threadIdx.x >> 5, lane = threadIdx.x & 31;
    int hp = w & 3, c = w >> 2, h0 = hp * 2;
    int seg = blockIdx.y * 2 + c;
    int ts = (seg * Tlen) >> 3, te = ((seg + 1) * Tlen) >> 3;

    u64x2 qtr[2][8];
#pragma unroll
    for (int hh = 0; hh < 2; hh++) {
        const float4* qp = (const float4*)(qt + ((size_t)n * HH + h0 + hh) * DDIM);
#pragma unroll
        for (int qi = 0; qi < 4; qi++) {
            float4 v = qp[lane + 32 * qi];
            qtr[hh][2*qi] = pk2(v.x, v.y); qtr[hh][2*qi+1] = pk2(v.z, v.w);
        }
    }
    float qb[2];
#pragma unroll
    for (int hh = 0; hh < 2; hh++) {
        int h = h0 + hh;
        float p = qs[(size_t)n * DDIM + h*64 + lane]      * bk[h*64 + lane]
                + qs[(size_t)n * DDIM + h*64 + 32 + lane] * bk[h*64 + 32 + lane];
#pragma unroll
        for (int off = 16; off > 0; off >>= 1)
            p += __shfl_xor_sync(0xffffffffu, p, off);
        qb[hh] = p;
    }
    float mh[2] = {-1e30f, -1e30f}, sh[2] = {0.f, 0.f};
    u64x2 acc[2][8];
#pragma unroll
    for (int hh = 0; hh < 2; hh++)
#pragma unroll
        for (int qi = 0; qi < 8; qi++) acc[hh][qi] = pk2(0.f, 0.f);

    const float* kvn = kv + (size_t)n * DDIM;
    const float4* erow = (const float4*)(extra + (size_t)n * DDIM);
    const unsigned char* mk = mask ? mask + (size_t)n * Tlen : nullptr;

    u64x2 A[8], B[8];
    if (ts < te) f_load(A, kvn, erow, ts, Tmain, rs, lane);
    int t = ts;
    while (t < te) {
        if (t + 1 < te) f_load(B, kvn, erow, t + 1, Tmain, rs, lane);
        f_step(A, qtr, qb, (mk && mk[t]) ? -1e9f : 0.f, mh, sh, acc);
        t++;
        if (t >= te) break;
        if (t + 1 < te) f_load(A, kvn, erow, t + 1, Tmain, rs, lane);
        f_step(B, qtr, qb, (mk && mk[t]) ? -1e9f : 0.f, mh, sh, acc);
        t++;
    }
#pragma unroll
    for (int hh = 0; hh < 2; hh++) {
        size_t base = ((size_t)n * 8 + seg) * HH + h0 + hh;
        if (lane == 0) fst[base] = make_float2(mh[hh], sh[hh]);
        float4* op = (float4*)(facc + base * DDIM);
#pragma unroll
        for (int qi = 0; qi < 4; qi++) {
            float2 a = upk(acc[hh][2*qi]), b = upk(acc[hh][2*qi+1]);
            float4 v = {a.x, a.y, b.x, b.y};
            op[lane + 32 * qi] = v;
        }
    }
}

__global__ __launch_bounds__(256) void merge_kernel(
    const float* __restrict__ facc, const float2* __restrict__ fst,
    float* __restrict__ ctx)
{
    int n = blockIdx.x, w = threadIdx.x >> 5, lane = threadIdx.x & 31;
    float2 st[8]; float M = -1e30f;
#pragma unroll
    for (int s = 0; s < 8; s++) {
        st[s] = fst[((size_t)n * 8 + s) * HH + w];
        M = fmaxf(M, st[s].x);
    }
    float S = 0.f;
#pragma unroll
    for (int s = 0; s < 8; s++) S += st[s].y * __expf(st[s].x - M);
    float inv = 1.f / S;
    float co[8];
#pragma unroll
    for (int s = 0; s < 8; s++) co[s] = __expf(st[s].x - M) * inv;
    float4 out[4];
#pragma unroll
    for (int qi = 0; qi < 4; qi++) out[qi] = make_float4(0.f, 0.f, 0.f, 0.f);
#pragma unroll
    for (int s = 0; s < 8; s++) {
        const float4* ap = (const float4*)(facc + (((size_t)n * 8 + s) * HH + w) * DDIM);
#pragma unroll
        for (int qi = 0; qi < 4; qi++) {
            float4 v = ap[lane + 32 * qi];
            out[qi].x += co[s]*v.x; out[qi].y += co[s]*v.y;
            out[qi].z += co[s]*v.z; out[qi].w += co[s]*v.w;
        }
    }
    float4* op = (float4*)(ctx + ((size_t)n * HH + w) * DDIM);
#pragma unroll
    for (int qi = 0; qi < 4; qi++) op[lane + 32 * qi] = out[qi];
}

// ---------------- host ----------------
static void gemm(const float* A, int lda, int aOffZ,
                 const float* W, int ldw, int wOffZ, bool wt,
                 float* C, int ldc, int cOffZ, long PS, const float* bias,
                 int Kloc, int KS, int Hz, int Mz, float scale, int relu)
{
    dim3 g(4, Mz / 64, Hz * KS);
    if (wt)
        gemm_kernel<true><<<g,256>>>(A,lda,aOffZ,W,ldw,wOffZ,C,ldc,cOffZ,PS,bias,Kloc,KS,scale,relu);
    else
        gemm_kernel<false><<<g,256>>>(A,lda,aOffZ,W,ldw,wOffZ,C,ldc,cOffZ,PS,bias,Kloc,KS,scale,relu);
}
static void red(const float* part, long PS, int KS, const float* bias,
                const float* res, float* C, int M, float scale, int relu)
{
    reduce_kernel<<<(NNH * M) / 512, 128>>>(part, PS, KS, bias, res, C, M, scale, relu);
}

extern "C" void kernel_launch(void* const* d_in, const int* in_sizes, int n_in,
                              void* d_out, int out_size)
{
    (void)in_sizes; (void)n_in; (void)out_size;
    const int*   toks   = (const int*)  d_in[0];
    const float* cached = (const float*)d_in[1];
    const float* memory = (const float*)d_in[2];
    const unsigned char* mmask = (const unsigned char*)d_in[3];
    const float* embd   = (const float*)d_in[4];
    const float* Wqkv_s = (const float*)d_in[5];
    const float* bqkv_s = (const float*)d_in[6];
    const float* Wo_s   = (const float*)d_in[7];
    const float* bo_s   = (const float*)d_in[8];
    const float* Wqkv_c = (const float*)d_in[9];
    const float* bqkv_c = (const float*)d_in[10];
    const float* Wo_c   = (const float*)d_in[11];
    const float* bo_c   = (const float*)d_in[12];
    const float* W1     = (const float*)d_in[13];
    const float* b1     = (const float*)d_in[14];
    const float* W2     = (const float*)d_in[15];
    const float* b2     = (const float*)d_in[16];
    const float* ln1w   = (const float*)d_in[17];
    const float* ln1b   = (const float*)d_in[18];
    const float* ln2w   = (const float*)d_in[19];
    const float* ln2b   = (const float*)d_in[20];
    const float* ln3w   = (const float*)d_in[21];
    const float* ln3b   = (const float*)d_in[22];
    const int*   offp   = (const int*)  d_in[23];
    float* dout = (float*)d_out;

    float *tgt,*q,*o,*qt,*ctx,*ff,*part,*facc; float2* fst;
    cudaGetSymbolAddress((void**)&tgt,  g_tgt);
    cudaGetSymbolAddress((void**)&q,    g_q);
    cudaGetSymbolAddress((void**)&o,    g_o);
    cudaGetSymbolAddress((void**)&qt,   g_qt);
    cudaGetSymbolAddress((void**)&ctx,  g_ctx);
    cudaGetSymbolAddress((void**)&ff,   g_ff);
    cudaGetSymbolAddress((void**)&part, g_part);
    cudaGetSymbolAddress((void**)&facc, g_facc);
    cudaGetSymbolAddress((void**)&fst,  g_fst);

    const long PS_D = (long)NNH * DDIM;
    embed_kernel<<<NNH, 128>>>(toks, embd, offp, tgt);

    for (int l = 0; l < LL; l++) {
        for (int pass = 0; pass < 2; pass++) {
            const float* Wqkv = (pass==0 ? Wqkv_s : Wqkv_c) + (size_t)l*3*DDIM*DDIM;
            const float* bqkv = (pass==0 ? bqkv_s : bqkv_c) + (size_t)l*3*DDIM;
            const float* Wo   = (pass==0 ? Wo_s   : Wo_c)   + (size_t)l*DDIM*DDIM;
            const float* bo   = (pass==0 ? bo_s   : bo_c)   + (size_t)l*DDIM;
            const float* lw   = (pass==0 ? ln1w : ln2w) + (size_t)l*DDIM;
            const float* lb   = (pass==0 ? ln1b : ln2b) + (size_t)l*DDIM;
            const float* kv   = (pass==0) ? cached + (size_t)l*TT*NNH*DDIM : memory;
            int Tlen  = (pass==0) ? TT + 1 : SSL;
            int Tmain = (pass==0) ? TT : SSL;
            const unsigned char* mk = (pass==0) ? nullptr : mmask;

            // q = 0.125*(tgt @ Wq^T + bq), split-K 4
            gemm(tgt, DDIM,0, Wqkv, DDIM,0,false, part, DDIM,0, PS_D, nullptr,
                 DDIM/4,4, 1, DDIM, 1.f,0);
            red(part, PS_D, 4, bqkv, nullptr, q, DDIM, 0.125f, 0);
            // qt[n,h,:] = q[n,h*64:(h+1)*64] @ Wk_h  (WT path, z=head)
            gemm(q, DDIM, DHH, Wqkv + DDIM*DDIM, DDIM, DHH*DDIM, true,
                 qt, HH*DDIM, DDIM, 0, nullptr, DHH,1, HH, DDIM, 1.f,0);
            // flash + merge -> ctx
            flash_kernel<<<dim3(NNH,4),256>>>(qt, q, bqkv + DDIM, kv, tgt, mk,
                                              fst, facc, Tlen, Tmain, PS_D);
            merge_kernel<<<NNH,256>>>(facc, fst, ctx);
            // o[n, h*64+j] = Wv_h @ ctx[n,h,:] + bv, split-K 4 per head
            gemm(ctx, HH*DDIM, DDIM, Wqkv + 2*DDIM*DDIM, DDIM, DHH*DDIM, false,
                 part, DDIM, DHH, PS_D, nullptr, DDIM/4, 4, HH, DHH, 1.f, 0);
            red(part, PS_D, 4, bqkv + 2*DDIM, nullptr, o, DDIM, 1.f, 0);
            // attn = o @ Wo^T + bo + tgt, split-K 4, fused reduce+residual+LN
            gemm(o, DDIM,0, Wo, DDIM,0,false, part, DDIM,0, PS_D, nullptr,
                 DDIM/4,4, 1, DDIM, 1.f,0);
            ln_red_kernel<<<NNH,128>>>(part, PS_D, 4, bo, tgt, lw, lb, tgt);
        }
        // FFN
        const float* W1l = W1 + (size_t)l*DFF*DDIM;
        const float* W2l = W2 + (size_t)l*DDIM*DFF;
        gemm(tgt, DDIM,0, W1l, DDIM,0,false, part, DFF,0, (long)NNH*DFF, nullptr,
             DDIM/2,2, 1, DFF, 1.f,0);
        red(part, (long)NNH*DFF, 2, b1 + (size_t)l*DFF, nullptr, ff, DFF, 1.f, 1);
        gemm(ff, DFF,0, W2l, DFF,0,false, part, DDIM,0, PS_D, nullptr,
             DFF/8,8, 1, DDIM, 1.f,0);
        ln_red_kernel<<<NNH,128>>>(part, PS_D, 8, b2 + (size_t)l*DDIM, tgt,
                                   ln3w + (size_t)l*DDIM, ln3b + (size_t)l*DDIM,
                                   (l == LL-1) ? dout : tgt);
    }
}